// round 2
// baseline (speedup 1.0000x reference)
#include <cuda_runtime.h>
#include <math.h>

#define D 128
#define N_MID 6
#define N_MAX 131072

// ---------------- preprocessed weights (device globals, no runtime alloc) ----------------
__device__ __align__(16) float d_AU0[2][D];           // [k][o]  k=0:x, k=1:theta
__device__ __align__(16) float d_B0[D];
__device__ __align__(16) float d_W0[D * D];           // [k][o] = softmax(w0)[o][k]
__device__ __align__(16) float d_AUM[N_MID][D * D];   // [k][o] = exp(laM[o])*softmax(uM)[o][k]
__device__ __align__(16) float d_BM[N_MID][D];
__device__ __align__(16) float d_WM[N_MID][D * D];    // [k][o]
__device__ __align__(16) float d_auL[D];
__device__ float d_bL;
__device__ __align__(16) float d_theta[N_MAX];

__device__ __forceinline__ float sigmoidf(float x) {
    return __fdividef(1.0f, 1.0f + __expf(-x));
}

// ---------------- weight preprocessing: row softmax + exp(log_a) folding ----------------
__global__ void prep_kernel(const float* __restrict__ u0, const float* __restrict__ w0,
                            const float* __restrict__ la0, const float* __restrict__ b0,
                            const float* __restrict__ uM, const float* __restrict__ wM,
                            const float* __restrict__ laM, const float* __restrict__ bM,
                            const float* __restrict__ uL, const float* __restrict__ laL,
                            const float* __restrict__ bL) {
    const int b = blockIdx.x;
    const int o = threadIdx.x;  // 128 threads
    if (b == 0) {
        // first layer: softmax over 2 inputs, scaled by exp(la0)
        float v0 = u0[o * 2 + 0], v1 = u0[o * 2 + 1];
        float m = fmaxf(v0, v1);
        float e0 = expf(v0 - m), e1 = expf(v1 - m);
        float a = expf(la0[o]);
        float inv = a / (e0 + e1);
        d_AU0[0][o] = e0 * inv;
        d_AU0[1][o] = e1 * inv;
        d_B0[o] = b0[o];
        if (o == 0) {
            // last layer: uL [1,128] row-softmax, times exp(laL). softmax(wL[1,1]) == 1.
            float mm = -1e30f;
            for (int k = 0; k < D; k++) mm = fmaxf(mm, uL[k]);
            float s = 0.f;
            for (int k = 0; k < D; k++) s += expf(uL[k] - mm);
            float inv2 = expf(laL[0]) / s;
            for (int k = 0; k < D; k++) d_auL[k] = expf(uL[k] - mm) * inv2;
            d_bL = bL[0];
        }
    } else if (b == 1) {
        const float* row = w0 + o * D;
        float m = -1e30f;
        for (int k = 0; k < D; k++) m = fmaxf(m, row[k]);
        float s = 0.f;
        for (int k = 0; k < D; k++) s += expf(row[k] - m);
        float inv = 1.0f / s;
        for (int k = 0; k < D; k++) d_W0[k * D + o] = expf(row[k] - m) * inv;
    } else if (b < 2 + N_MID) {
        const int mI = b - 2;
        const float* row = uM + mI * D * D + o * D;
        float m = -1e30f;
        for (int k = 0; k < D; k++) m = fmaxf(m, row[k]);
        float s = 0.f;
        for (int k = 0; k < D; k++) s += expf(row[k] - m);
        float inv = expf(laM[mI * D + o]) / s;
        for (int k = 0; k < D; k++) d_AUM[mI][k * D + o] = expf(row[k] - m) * inv;
        d_BM[mI][o] = bM[mI * D + o];
    } else {
        const int mI = b - 2 - N_MID;
        const float* row = wM + mI * D * D + o * D;
        float m = -1e30f;
        for (int k = 0; k < D; k++) m = fmaxf(m, row[k]);
        float s = 0.f;
        for (int k = 0; k < D; k++) s += expf(row[k] - m);
        float inv = 1.0f / s;
        for (int k = 0; k < D; k++) d_WM[mI][k * D + o] = expf(row[k] - m) * inv;
    }
}

// ---------------- feature MLP: theta[i] = MLP_1_50_50_1(fy0[i]) ----------------
__global__ void __launch_bounds__(256) theta_kernel(
    const float* __restrict__ fy0,
    const float* __restrict__ W1, const float* __restrict__ b1,
    const float* __restrict__ W2, const float* __restrict__ b2,
    const float* __restrict__ W3, const float* __restrict__ b3, int n) {
    __shared__ float sW1[50], sb1[50], sW2[2500], sb2[50], sW3[50];
    const int tid = threadIdx.x;
    if (tid < 50) { sW1[tid] = W1[tid]; sb1[tid] = b1[tid]; sb2[tid] = b2[tid]; sW3[tid] = W3[tid]; }
    for (int i = tid; i < 2500; i += 256) sW2[i] = W2[i];
    __syncthreads();
    const int i = blockIdx.x * 256 + tid;
    if (i >= n) return;
    const float v = fy0[i];
    float h1[50];
#pragma unroll
    for (int j = 0; j < 50; j++) h1[j] = fmaxf(fmaf(sW1[j], v, sb1[j]), 0.0f);
    float th = b3[0];
    for (int j = 0; j < 50; j++) {
        const float* wr = sW2 + j * 50;
        float a0 = sb2[j], a1 = 0.f, a2 = 0.f, a3 = 0.f;
#pragma unroll
        for (int k = 0; k < 48; k += 4) {
            a0 = fmaf(wr[k + 0], h1[k + 0], a0);
            a1 = fmaf(wr[k + 1], h1[k + 1], a1);
            a2 = fmaf(wr[k + 2], h1[k + 2], a2);
            a3 = fmaf(wr[k + 3], h1[k + 3], a3);
        }
        a0 = fmaf(wr[48], h1[48], a0);
        a1 = fmaf(wr[49], h1[49], a1);
        float acc = (a0 + a1) + (a2 + a3);
        th = fmaf(sW3[j], fmaxf(acc, 0.0f), th);
    }
    d_theta[i] = th;
}

// ---------------- fused 128x128x128 SGEMM core (A, C transposed k-major in SMEM) ----------------
// C[o][r] = (ACT ? sigmoid(sum_k A[k][r]*B[k][o] + bias[o]) : sum_k A[k][r]*B[k][o])
template <bool ACT>
__device__ __forceinline__ void gemm128(const float* __restrict__ A,
                                        const float* __restrict__ Bglob,
                                        float* __restrict__ C,
                                        const float* __restrict__ bias,
                                        float* __restrict__ sW) {
    const int tid = threadIdx.x;
    __syncthreads();  // prior consumers of sW / prior writes to C done
    {
        const float4* src = (const float4*)Bglob;
        float4* dst = (float4*)sW;
#pragma unroll
        for (int i = 0; i < 16; i++) dst[tid + 256 * i] = src[tid + 256 * i];
    }
    __syncthreads();
    const int tx = tid & 15;   // row-group (fast across lanes -> coalesced SMEM)
    const int ty = tid >> 4;   // col-group
    const float* Ap = A + tx * 8;
    const float* Bp = sW + ty * 8;
    float acc[8][8];
#pragma unroll
    for (int i = 0; i < 8; i++)
#pragma unroll
        for (int j = 0; j < 8; j++) acc[i][j] = 0.0f;

#pragma unroll 8
    for (int k = 0; k < D; k++) {
        float4 a0 = *(const float4*)(Ap + k * D);
        float4 a1 = *(const float4*)(Ap + k * D + 4);
        float4 b0 = *(const float4*)(Bp + k * D);
        float4 b1 = *(const float4*)(Bp + k * D + 4);
        float av[8] = {a0.x, a0.y, a0.z, a0.w, a1.x, a1.y, a1.z, a1.w};
        float bv[8] = {b0.x, b0.y, b0.z, b0.w, b1.x, b1.y, b1.z, b1.w};
#pragma unroll
        for (int i = 0; i < 8; i++)
#pragma unroll
            for (int j = 0; j < 8; j++) acc[i][j] = fmaf(av[i], bv[j], acc[i][j]);
    }

#pragma unroll
    for (int j = 0; j < 8; j++) {
        const int o = ty * 8 + j;
        float outv[8];
        if (ACT) {
            const float bj = bias[o];
#pragma unroll
            for (int i = 0; i < 8; i++) outv[i] = sigmoidf(acc[i][j] + bj);
        } else {
#pragma unroll
            for (int i = 0; i < 8; i++) outv[i] = acc[i][j];
        }
        *(float4*)(C + o * D + tx * 8) = make_float4(outv[0], outv[1], outv[2], outv[3]);
        *(float4*)(C + o * D + tx * 8 + 4) = make_float4(outv[4], outv[5], outv[6], outv[7]);
    }
}

// ---------------- fully fused per-128-row-slab kernel ----------------
__global__ void __launch_bounds__(256, 1) fused_kernel(const float* __restrict__ x,
                                                       float* __restrict__ out, int n) {
    extern __shared__ float smem[];
    float* hA = smem;             // [k][r] 128x128
    float* hB = smem + 16384;     // [k][r]
    float* sW = smem + 32768;     // weight stage [k][o]
    float* sx = smem + 49152;     // 128
    float* sth = sx + 128;        // 128

    const int tid = threadIdx.x;
    const int r0 = blockIdx.x * D;
    if (tid < D) { sx[tid] = x[r0 + tid]; sth[tid] = d_theta[r0 + tid]; }
    __syncthreads();

    // first layer (in=2): sigmoid(x*au0 + theta*au1 + b0), stored transposed into hA[o][r]
#pragma unroll
    for (int it = 0; it < 64; it++) {
        const int idx = tid + it * 256;
        const int o = idx >> 7, r = idx & 127;
        float inner = fmaf(sx[r], d_AU0[0][o], fmaf(sth[r], d_AU0[1][o], d_B0[o]));
        hA[o * D + r] = sigmoidf(inner);
    }

    // layer0 W matmul (no activation)
    gemm128<false>(hA, d_W0, hB, nullptr, sW);

    // six middle layers
#pragma unroll 1
    for (int m = 0; m < N_MID; m++) {
        gemm128<true>(hB, d_AUM[m], hA, d_BM[m], sW);
        gemm128<false>(hA, d_WM[m], hB, nullptr, sW);
    }

    __syncthreads();
    // last layer: out[r] = sigmoid(sum_k hB[k][r]*auL[k] + bL)
    if (tid < D) {
        float acc = d_bL;
#pragma unroll 8
        for (int k = 0; k < D; k++) acc = fmaf(hB[k * D + tid], d_auL[k], acc);
        out[r0 + tid] = sigmoidf(acc);
    }
}

// ---------------- launch ----------------
extern "C" void kernel_launch(void* const* d_in, const int* in_sizes, int n_in,
                              void* d_out, int out_size) {
    const float* x   = (const float*)d_in[0];
    const float* fy0 = (const float*)d_in[1];
    const float* u0  = (const float*)d_in[2];
    const float* w0  = (const float*)d_in[3];
    const float* la0 = (const float*)d_in[4];
    const float* b0  = (const float*)d_in[5];
    const float* uM  = (const float*)d_in[6];
    const float* wM  = (const float*)d_in[7];
    const float* laM = (const float*)d_in[8];
    const float* bM  = (const float*)d_in[9];
    const float* uL  = (const float*)d_in[10];
    // d_in[11] = wL: softmax of a [1,1] row is exactly 1.0 -> multiplicative identity
    const float* laL = (const float*)d_in[12];
    const float* bL  = (const float*)d_in[13];
    const float* W1  = (const float*)d_in[14];
    const float* b1  = (const float*)d_in[15];
    const float* W2  = (const float*)d_in[16];
    const float* b2  = (const float*)d_in[17];
    const float* W3  = (const float*)d_in[18];
    const float* b3  = (const float*)d_in[19];
    float* out = (float*)d_out;
    const int n = in_sizes[0];

    const int smem_bytes = (16384 * 3 + 256) * 4;  // 197632 B
    cudaFuncSetAttribute(fused_kernel, cudaFuncAttributeMaxDynamicSharedMemorySize, smem_bytes);

    prep_kernel<<<2 + 2 * N_MID, 128>>>(u0, w0, la0, b0, uM, wM, laM, bM, uL, laL, bL);
    theta_kernel<<<(n + 255) / 256, 256>>>(fy0, W1, b1, W2, b2, W3, b3, n);
    fused_kernel<<<n / D, 256, smem_bytes>>>(x, out, n);
}